// round 1
// baseline (speedup 1.0000x reference)
#include <cuda_runtime.h>
#include <math.h>
#include <stdint.h>

// ---------------- problem constants ----------------
#define BATCH  32
#define HEADS  12
#define SEQ    512
#define LHALF  256
#define DMODEL 768
#define HH     384          // hidden per direction
#define G4     1536         // 4*HH gates
#define DIN    1536         // 2*DMODEL LSTM input
#define BH     384          // BATCH*HEADS
#define TT     6            // SLIDER
#define EPSV   1e-9f

// ---------------- device scratch (no allocs allowed) ----------------
__device__ int   g_master[BH * 2];                     // [bh][half]
__device__ float g_slide[(size_t)BH * TT * DIN];       // 2304 x 1536
__device__ float g_gatesX[(size_t)BH * TT * 2 * G4];   // 2304 x 3072 (fwd | rev)
__device__ float g_gtmp[(size_t)2 * BH * G4];          // per-step h @ whh^T
__device__ float g_h[(size_t)2 * BH * HH];
__device__ float g_c[(size_t)2 * BH * HH];
__device__ float g_compose[(size_t)BH * TT * DMODEL];  // [n][t][fwd|bwd]
__device__ float g_lrep[(size_t)BATCH * DMODEL];

// ---------------- helpers ----------------
__device__ __forceinline__ float sigf(float x) { return 1.0f / (1.0f + expf(-x)); }

__device__ __forceinline__ int window_start(int pos) {
    pos = min(max(pos, 1), LHALF - 2);
    int l = TT / 2;                          // 3
    if (pos - TT / 2 <= 0) l = pos - 1;
    int r = TT - l;
    if (pos + r >= LHALF - 1) l = TT - (LHALF - pos - 2);
    return pos - l;
}

// ---------------- K1: masters (row-sum + argmax over 256x256 quadrant) ----------------
__global__ void masters_kernel(const float* __restrict__ att, const int* __restrict__ sents) {
    int bid  = blockIdx.x;           // [0, BH*2)
    int half = bid & 1;
    int bh   = bid >> 1;
    int b    = bh / HEADS;

    __shared__ unsigned char seps[LHALF];
    __shared__ float rowsum[LHALF];

    int tid = threadIdx.x;           // 256 threads
    // sep flags on key axis (applies to this half's key range)
    {
        int j = half * LHALF + tid;
        seps[tid] = (sents[b * SEQ + j] == 102) ? 1 : 0;
    }
    __syncthreads();

    const float* base = att + ((size_t)bh * SEQ + (size_t)half * LHALF) * SEQ + (size_t)half * LHALF;

    int warp = tid >> 5, lane = tid & 31;
    for (int row = warp; row < LHALF; row += 8) {
        const float* rp = base + (size_t)row * SEQ;
        float s = 0.0f;
        #pragma unroll
        for (int k = 0; k < 8; k++) {
            int j = lane + 32 * k;
            float v = rp[j];
            s += seps[j] ? EPSV : v;
        }
        #pragma unroll
        for (int off = 16; off > 0; off >>= 1)
            s += __shfl_down_sync(0xffffffffu, s, off);
        if (lane == 0) rowsum[row] = s;
    }
    __syncthreads();

    // argmax, first index wins ties
    __shared__ float bv[LHALF];
    __shared__ int   bix[LHALF];
    bv[tid]  = rowsum[tid];
    bix[tid] = tid;
    __syncthreads();
    for (int off = 128; off > 0; off >>= 1) {
        if (tid < off) {
            float vo = bv[tid + off];
            int   io = bix[tid + off];
            if (vo > bv[tid] || (vo == bv[tid] && io < bix[tid])) { bv[tid] = vo; bix[tid] = io; }
        }
        __syncthreads();
    }
    if (tid == 0) g_master[bh * 2 + half] = bix[0];
}

// ---------------- K2: gather windows -> slide ----------------
__global__ void build_slide(const float* __restrict__ logits, const int* __restrict__ mask) {
    int bh = blockIdx.x;             // [0, BH)
    int b  = bh / HEADS;
    __shared__ int sa, sb;
    if (threadIdx.x == 0) {
        sa = window_start(g_master[bh * 2 + 0]);
        sb = window_start(g_master[bh * 2 + 1]);
    }
    __syncthreads();

    for (int idx = threadIdx.x; idx < TT * DIN; idx += blockDim.x) {
        int t = idx / DIN, f = idx % DIN;
        float v;
        if (f < DMODEL) {
            int row = sa + t;
            v = (mask[b * SEQ + row] == 0) ? EPSV
                : logits[((size_t)b * SEQ + row) * DMODEL + f];
        } else {
            int row = LHALF + sb + t;
            v = (mask[b * SEQ + row] == 0) ? EPSV
                : logits[((size_t)b * SEQ + row) * DMODEL + (f - DMODEL)];
        }
        g_slide[(size_t)bh * (TT * DIN) + idx] = v;
    }
}

// ---------------- K3: zero h/c state ----------------
__global__ void zero_hc() {
    int i = blockIdx.x * blockDim.x + threadIdx.x;
    if (i < 2 * BH * HH) { g_h[i] = 0.0f; g_c[i] = 0.0f; }
}

// ---------------- K4: input GEMM  C[2304,3072] = slide @ [Wf;Wr]^T + biases ----------------
__global__ void input_gemm(const float* __restrict__ Wf, const float* __restrict__ Wr,
                           const float* __restrict__ bihf, const float* __restrict__ bhhf,
                           const float* __restrict__ bihr, const float* __restrict__ bhhr) {
    const int K = DIN;
    __shared__ float As[16][65];
    __shared__ float Bs[16][65];

    int bm = blockIdx.y * 64;
    int bn = blockIdx.x * 64;            // global n in [0, 3072)
    bool rev = (bn >= G4);
    const float* W = rev ? Wr : Wf;
    int bnl = rev ? (bn - G4) : bn;

    int tid = threadIdx.x;               // 256 threads
    int tx = tid & 15, ty = tid >> 4;
    float acc[4][4] = {};

    for (int k0 = 0; k0 < K; k0 += 16) {
        #pragma unroll
        for (int i = 0; i < 4; i++) {
            int e = tid + i * 256;
            int r = e >> 4, c = e & 15;
            As[c][r] = g_slide[(size_t)(bm + r) * K + k0 + c];
            Bs[c][r] = W[(size_t)(bnl + r) * K + k0 + c];
        }
        __syncthreads();
        #pragma unroll
        for (int kk = 0; kk < 16; kk++) {
            float a[4], bb[4];
            #pragma unroll
            for (int i = 0; i < 4; i++) a[i] = As[kk][ty * 4 + i];
            #pragma unroll
            for (int j = 0; j < 4; j++) bb[j] = Bs[kk][tx * 4 + j];
            #pragma unroll
            for (int i = 0; i < 4; i++)
                #pragma unroll
                for (int j = 0; j < 4; j++)
                    acc[i][j] += a[i] * bb[j];
        }
        __syncthreads();
    }

    #pragma unroll
    for (int i = 0; i < 4; i++) {
        int m = bm + ty * 4 + i;
        #pragma unroll
        for (int j = 0; j < 4; j++) {
            int nl = bnl + tx * 4 + j;
            float bias = rev ? (bihr[nl] + bhhr[nl]) : (bihf[nl] + bhhf[nl]);
            g_gatesX[(size_t)m * (2 * G4) + bn + tx * 4 + j] = acc[i][j] + bias;
        }
    }
}

// ---------------- K5: per-step recurrent GEMM  gtmp[dir] = h[dir] @ whh[dir]^T ----------------
__global__ void hgemm(const float* __restrict__ whhf, const float* __restrict__ whhr) {
    const int K = HH;
    int dir = blockIdx.z;
    const float* A = g_h + (size_t)dir * BH * HH;       // 384 x 384
    const float* W = dir ? whhr : whhf;                  // 1536 x 384
    float* C = g_gtmp + (size_t)dir * BH * G4;           // 384 x 1536

    __shared__ float As[16][65];
    __shared__ float Bs[16][65];

    int bm = blockIdx.y * 64;
    int bn = blockIdx.x * 64;
    int tid = threadIdx.x;
    int tx = tid & 15, ty = tid >> 4;
    float acc[4][4] = {};

    for (int k0 = 0; k0 < K; k0 += 16) {
        #pragma unroll
        for (int i = 0; i < 4; i++) {
            int e = tid + i * 256;
            int r = e >> 4, c = e & 15;
            As[c][r] = A[(size_t)(bm + r) * K + k0 + c];
            Bs[c][r] = W[(size_t)(bn + r) * K + k0 + c];
        }
        __syncthreads();
        #pragma unroll
        for (int kk = 0; kk < 16; kk++) {
            float a[4], bb[4];
            #pragma unroll
            for (int i = 0; i < 4; i++) a[i] = As[kk][ty * 4 + i];
            #pragma unroll
            for (int j = 0; j < 4; j++) bb[j] = Bs[kk][tx * 4 + j];
            #pragma unroll
            for (int i = 0; i < 4; i++)
                #pragma unroll
                for (int j = 0; j < 4; j++)
                    acc[i][j] += a[i] * bb[j];
        }
        __syncthreads();
    }

    #pragma unroll
    for (int i = 0; i < 4; i++)
        #pragma unroll
        for (int j = 0; j < 4; j++)
            C[(size_t)(bm + ty * 4 + i) * G4 + bn + tx * 4 + j] = acc[i][j];
}

// ---------------- K6: per-step LSTM pointwise (both directions) ----------------
__global__ void lstm_point(int s) {
    int idx = blockIdx.x * blockDim.x + threadIdx.x;    // 2*384*384
    if (idx >= 2 * BH * HH) return;
    int dir = idx / (BH * HH);
    int r   = idx % (BH * HH);
    int n   = r / HH;
    int j   = r % HH;
    int t   = dir ? (TT - 1 - s) : s;                   // reverse scan alignment

    const float* G0 = g_gatesX + ((size_t)(n * TT + t)) * (2 * G4) + (size_t)dir * G4;
    const float* T0 = g_gtmp + (size_t)dir * BH * G4 + (size_t)n * G4;

    float gi = G0[j]            + T0[j];
    float gf = G0[HH + j]       + T0[HH + j];
    float gg = G0[2 * HH + j]   + T0[2 * HH + j];
    float go = G0[3 * HH + j]   + T0[3 * HH + j];

    size_t st = (size_t)dir * BH * HH + (size_t)n * HH + j;
    float c = sigf(gf) * g_c[st] + sigf(gi) * tanhf(gg);
    float h = sigf(go) * tanhf(c);
    g_c[st] = c;
    g_h[st] = h;
    g_compose[((size_t)n * TT + t) * DMODEL + dir * HH + j] = h;
}

// ---------------- K7: logits_rep (mean of logits with window/mask replacement) ----------------
__global__ void logits_rep_kernel(const float* __restrict__ logits, const int* __restrict__ mask) {
    int b = blockIdx.x;
    int tid = threadIdx.x;                              // 256

    __shared__ unsigned char repl[SEQ];
    for (int i = tid; i < SEQ; i += blockDim.x) repl[i] = 0;
    __syncthreads();
    if (tid < 2 * HEADS) {
        int h = tid >> 1, half = tid & 1;
        int st = window_start(g_master[(b * HEADS + h) * 2 + half]);
        int base = half * LHALF + st;
        for (int k = 0; k < TT; k++) repl[base + k] = 1;   // benign same-value races
    }
    __syncthreads();
    for (int sPos = tid; sPos < SEQ; sPos += blockDim.x)
        repl[sPos] = (repl[sPos] && mask[b * SEQ + sPos] == 0) ? 1 : 0;
    __syncthreads();

    for (int d = tid; d < DMODEL; d += blockDim.x) {
        float acc = 0.0f;
        for (int sPos = 0; sPos < SEQ; sPos++) {
            float v = logits[((size_t)b * SEQ + sPos) * DMODEL + d];
            acc += repl[sPos] ? EPSV : v;
        }
        g_lrep[(size_t)b * DMODEL + d] = acc * (1.0f / (float)SEQ);
    }
}

// ---------------- K8: final FC (2 outputs) + softmax ----------------
__global__ void final_kernel(const float* __restrict__ fcw, const float* __restrict__ fcb,
                             float* __restrict__ out) {
    int b = blockIdx.x;
    int tid = threadIdx.x;                              // 256
    const int NF = DMODEL * (HEADS + 1);                // 9984
    float a0 = 0.0f, a1 = 0.0f;

    for (int j = tid; j < NF; j += 256) {
        float x;
        if (j < HEADS * DMODEL) {
            int h = j / DMODEL, d = j % DMODEL;
            int n = b * HEADS + h;
            const float* cp = g_compose + (size_t)n * TT * DMODEL + d;
            float s = 0.0f;
            #pragma unroll
            for (int t = 0; t < TT; t++) s += cp[(size_t)t * DMODEL];
            x = s * (1.0f / (float)TT);
        } else {
            x = g_lrep[(size_t)b * DMODEL + (j - HEADS * DMODEL)];
        }
        a0 += x * fcw[j];
        a1 += x * fcw[NF + j];
    }

    __shared__ float s0[256], s1[256];
    s0[tid] = a0; s1[tid] = a1;
    __syncthreads();
    for (int off = 128; off > 0; off >>= 1) {
        if (tid < off) { s0[tid] += s0[tid + off]; s1[tid] += s1[tid + off]; }
        __syncthreads();
    }
    if (tid == 0) {
        float l0 = s0[0] + fcb[0], l1 = s1[0] + fcb[1];
        float m = fmaxf(l0, l1);
        float e0 = expf(l0 - m), e1 = expf(l1 - m);
        float inv = 1.0f / (e0 + e1);
        out[b * 2 + 0] = e0 * inv;
        out[b * 2 + 1] = e1 * inv;
    }
}

// ---------------- launch ----------------
extern "C" void kernel_launch(void* const* d_in, const int* in_sizes, int n_in,
                              void* d_out, int out_size) {
    const int*   sents = (const int*)d_in[0];
    const float* att   = (const float*)d_in[1];
    const float* logits= (const float*)d_in[2];
    const int*   mask  = (const int*)d_in[3];
    const float* wih_f = (const float*)d_in[4];
    const float* whh_f = (const float*)d_in[5];
    const float* bih_f = (const float*)d_in[6];
    const float* bhh_f = (const float*)d_in[7];
    const float* wih_r = (const float*)d_in[8];
    const float* whh_r = (const float*)d_in[9];
    const float* bih_r = (const float*)d_in[10];
    const float* bhh_r = (const float*)d_in[11];
    const float* fc_w  = (const float*)d_in[12];
    const float* fc_b  = (const float*)d_in[13];
    float* out = (float*)d_out;

    masters_kernel<<<BH * 2, 256>>>(att, sents);
    build_slide<<<BH, 256>>>(logits, mask);
    zero_hc<<<(2 * BH * HH + 255) / 256, 256>>>();
    input_gemm<<<dim3(48, 36), 256>>>(wih_f, wih_r, bih_f, bhh_f, bih_r, bhh_r);
    for (int s = 0; s < TT; s++) {
        hgemm<<<dim3(G4 / 64, BH / 64, 2), 256>>>(whh_f, whh_r);
        lstm_point<<<(2 * BH * HH + 255) / 256, 256>>>(s);
    }
    logits_rep_kernel<<<BATCH, 256>>>(logits, mask);
    final_kernel<<<BATCH, 256>>>(fc_w, fc_b, out);
}